// round 14
// baseline (speedup 1.0000x reference)
#include <cuda_runtime.h>
#include <cuda_bf16.h>
#include <math.h>
#include <stdint.h>

// Problem constants
#define B_  32
#define S_  1024
#define D_  256
#define N_  32
#define C_  64
#define M_  (B_*S_)

// pass kernel tiling (tensor-core version)
#define SCH 32                // s-values per block
#define CHUNKS (S_/SCH)       // 32
#define TPB 256               // 8 warps
#define XPB 528               // x smem row pitch BYTES (264 bf16; 33 x 16B, odd)
#define PPB 528               // p smem row pitch bytes
#define CTPB 80               // cT row pitch bytes (40 bf16; 5 x 16B, odd)
#define CPAD 36               // agree fp32 row stride (floats)

// smem byte offsets; cS (4608 B) aliases cth+ctl (5120 B) — live ranges disjoint
#define O_XH  0
#define O_XL  (O_XH + SCH*XPB)       // 16896
#define O_PH  (O_XL + SCH*XPB)       // 33792
#define O_PL  (O_PH + N_*PPB)        // 50688
#define O_CS  (O_PL + N_*PPB)        // 67584
#define O_CTH O_CS                   // 67584 (alias)
#define O_CTL (O_CTH + N_*CTPB)      // 70144
#define PASS_SMEM (O_CTL + N_*CTPB)  // 72704 B -> 3 CTAs/SM (218112 total)

// capsule: 4 b's per block, 512 threads, grid (N_, B_/4) = 256 blocks
#define WPAD 68               // W smem row stride (floats); 17 float4/row
#define CB 4                  // b's per capsule block
#define CTPB_THREADS 512
// sW + sy + ss(2 halves) + sv
#define CAPS_SMEM ((D_*WPAD + CB*D_ + 2*CB*C_ + CB*C_) * 4)  // 76800 B

// ---------------- scratch (device globals; no runtime allocation) ----------
__device__ float          g_y0p[8*B_*D_];     // per-chunk partials of (1/N) sum_s x
__device__ float          g_ya[B_*N_*D_];     // y for iter1
__device__ float          g_yb[B_*N_*D_];     // y for iter2
__device__ float          g_v [B_*N_*C_];
__device__ float          g_logits[B_*S_*N_];
__device__ __nv_bfloat16  g_phi[B_*N_*D_];
__device__ __nv_bfloat16  g_plo[B_*N_*D_];

// ---------------- PTX helpers ----------------------------------------------
__device__ __forceinline__ uint32_t smem_u32(const void* p) {
    uint32_t a;
    asm("{ .reg .u64 t; cvta.to.shared.u64 t, %1; cvt.u32.u64 %0, t; }" : "=r"(a) : "l"(p));
    return a;
}
#define LDM_X4(r0,r1,r2,r3,a) \
    asm volatile("ldmatrix.sync.aligned.m8n8.x4.shared.b16 {%0,%1,%2,%3}, [%4];" \
        : "=r"(r0),"=r"(r1),"=r"(r2),"=r"(r3) : "r"(a))
#define LDM_X2(r0,r1,a) \
    asm volatile("ldmatrix.sync.aligned.m8n8.x2.shared.b16 {%0,%1}, [%2];" \
        : "=r"(r0),"=r"(r1) : "r"(a))
#define LDM_X4T(r0,r1,r2,r3,a) \
    asm volatile("ldmatrix.sync.aligned.m8n8.x4.trans.shared.b16 {%0,%1,%2,%3}, [%4];" \
        : "=r"(r0),"=r"(r1),"=r"(r2),"=r"(r3) : "r"(a))
__device__ __forceinline__ void mma_bf16(float* c, uint32_t a0, uint32_t a1, uint32_t a2,
                                         uint32_t a3, uint32_t b0, uint32_t b1) {
    asm volatile(
        "mma.sync.aligned.m16n8k16.row.col.f32.bf16.bf16.f32 "
        "{%0,%1,%2,%3}, {%4,%5,%6,%7}, {%8,%9}, {%0,%1,%2,%3};"
        : "+f"(c[0]), "+f"(c[1]), "+f"(c[2]), "+f"(c[3])
        : "r"(a0), "r"(a1), "r"(a2), "r"(a3), "r"(b0), "r"(b1));
}
__device__ __forceinline__ void red_add_v2(float* p, float a, float b) {
    asm volatile("red.global.add.v2.f32 [%0], {%1, %2};"
        :: "l"(__cvta_generic_to_global(p)), "f"(a), "f"(b) : "memory");
}

// split a float4 into hi/lo bf16x2-pairs (uint2 each)
__device__ __forceinline__ void split4(float4 v, uint2& hh, uint2& ll) {
    __nv_bfloat162 h01 = __float22bfloat162_rn(make_float2(v.x, v.y));
    __nv_bfloat162 h23 = __float22bfloat162_rn(make_float2(v.z, v.w));
    __nv_bfloat162 l01 = __float22bfloat162_rn(make_float2(
        v.x - __bfloat162float(h01.x), v.y - __bfloat162float(h01.y)));
    __nv_bfloat162 l23 = __float22bfloat162_rn(make_float2(
        v.z - __bfloat162float(h23.x), v.w - __bfloat162float(h23.y)));
    hh = make_uint2(*(uint32_t*)&h01, *(uint32_t*)&h23);
    ll = make_uint2(*(uint32_t*)&l01, *(uint32_t*)&l23);
}

// ---------------- y0 partials + ya/yb zeroing (read-only reduction) ---------
__global__ __launch_bounds__(256) void reduce_x_kernel(const float* __restrict__ x) {
    __shared__ float sred[256*4];
    const int b  = blockIdx.x >> 3;     // 32
    const int sg = blockIdx.x & 7;      // 8 groups x 128 s
    const int t  = threadIdx.x;
    const int q  = t & 63;              // d-quad: d = 4q
    const int rg = t >> 6;              // row-group 0..3
    const size_t rowbase = (size_t)b * S_ + sg * 128;

    {
        float4 z = make_float4(0.f, 0.f, 0.f, 0.f);
        ((float4*)g_ya)[blockIdx.x*256 + t] = z;
        ((float4*)g_yb)[blockIdx.x*256 + t] = z;
    }

    float4 a = make_float4(0.f, 0.f, 0.f, 0.f);
    #pragma unroll 8
    for (int it = 0; it < 32; it++) {
        const int s = it*4 + rg;
        const float4 v = *(const float4*)(x + (rowbase + s) * D_ + 4*q);
        a.x += v.x; a.y += v.y; a.z += v.z; a.w += v.w;
    }
    *(float4*)&sred[t*4] = a;
    __syncthreads();
    if (t < 64) {
        float4 r0 = *(const float4*)&sred[t*4];
        float4 r1 = *(const float4*)&sred[(t+64)*4];
        float4 r2 = *(const float4*)&sred[(t+128)*4];
        float4 r3 = *(const float4*)&sred[(t+192)*4];
        const float sc = 1.0f / (float)N_;
        float4 o = make_float4((r0.x+r1.x+r2.x+r3.x)*sc, (r0.y+r1.y+r2.y+r3.y)*sc,
                               (r0.z+r1.z+r2.z+r3.z)*sc, (r0.w+r1.w+r2.w+r3.w)*sc);
        *(float4*)&g_y0p[(sg*B_ + b)*D_ + 4*t] = o;
    }
}

// ---------------- capsule: s = y@W, v = squash(s), p = W@v (split-bf16) -----
// grid (N_, B_/CB) = (32, 8), 512 threads.
__global__ __launch_bounds__(CTPB_THREADS) void capsule_kernel(
        const float* __restrict__ W, int ysel, float* __restrict__ vout_ext, int compute_p) {
    extern __shared__ float sm[];
    float* sW = sm;                 // [D_][WPAD]
    float* sy = sW + D_*WPAD;       // [CB][D_]
    float* ss = sy + CB*D_;         // [2][CB][C_]  (two d-halves)
    float* sv = ss + 2*CB*C_;       // [CB][C_]

    const int n  = blockIdx.x;
    const int b0 = blockIdx.y * CB;
    const int t  = threadIdx.x;

    // W[n] load: 4096 float4 via LDG.128 -> STS.128, 8 per thread
    {
        const float4* Wn4 = (const float4*)(W + (size_t)n * D_ * C_);
        #pragma unroll
        for (int k = 0; k < 8; k += 4) {
            int j0 = t + (k+0)*512, j1 = t + (k+1)*512, j2 = t + (k+2)*512, j3 = t + (k+3)*512;
            float4 w0 = Wn4[j0];
            float4 w1 = Wn4[j1];
            float4 w2 = Wn4[j2];
            float4 w3 = Wn4[j3];
            *(float4*)&sW[(j0>>4)*WPAD + 4*(j0&15)] = w0;
            *(float4*)&sW[(j1>>4)*WPAD + 4*(j1&15)] = w1;
            *(float4*)&sW[(j2>>4)*WPAD + 4*(j2&15)] = w2;
            *(float4*)&sW[(j3>>4)*WPAD + 4*(j3&15)] = w3;
        }
    }
    // y rows for CB b's: CB*D_/512 = 2 per thread
    #pragma unroll
    for (int k = 0; k < CB*D_/CTPB_THREADS; k++) {
        int i = t + k*CTPB_THREADS;
        int bb = i >> 8, d = i & 255;
        if (ysel == 0) {
            float a = 0.f;
            #pragma unroll
            for (int p8 = 0; p8 < 8; p8++) a += g_y0p[(p8*B_ + b0+bb)*D_ + d];
            sy[bb*D_ + d] = a;
        } else {
            const float* ysrc = (ysel == 1) ? g_ya : g_yb;
            sy[bb*D_ + d] = ysrc[((size_t)(b0+bb)*N_ + n)*D_ + d];
        }
    }
    __syncthreads();

    // s[b][c] = sum_d y[b][d] * W[d][c]; thread = (c = t&63, bb = (t>>6)&3, half = t>>8)
    // each half covers 128 d's; partials combined at squash.
    {
        const int c = t & 63, bb = (t >> 6) & 3, half = t >> 8;
        const float* yr = sy + bb*D_ + half*128;
        const float* wr = sW + half*128*WPAD;
        float s0 = 0.f, s1 = 0.f, s2 = 0.f, s3 = 0.f;
        #pragma unroll 8
        for (int d = 0; d < 128; d += 4) {
            float4 yv = *(const float4*)(yr + d);
            s0 += yv.x * wr[(d+0)*WPAD + c];
            s1 += yv.y * wr[(d+1)*WPAD + c];
            s2 += yv.z * wr[(d+2)*WPAD + c];
            s3 += yv.w * wr[(d+3)*WPAD + c];
        }
        ss[half*CB*C_ + bb*C_ + c] = (s0 + s1) + (s2 + s3);
    }
    __syncthreads();

    // squash: warps 0..CB-1, warp wid handles b = b0+wid (combines d-halves)
    const int wid = t >> 5, lane = t & 31;
    if (wid < CB) {
        float a0 = ss[wid*C_ + lane]      + ss[CB*C_ + wid*C_ + lane];
        float a1 = ss[wid*C_ + 32 + lane] + ss[CB*C_ + wid*C_ + 32 + lane];
        float sq = a0*a0 + a1*a1;
        #pragma unroll
        for (int o = 16; o > 0; o >>= 1) sq += __shfl_xor_sync(0xffffffffu, sq, o);
        float sc = (sq / (1.f + sq)) * rsqrtf(sq + 1e-8f);
        float v0 = a0 * sc, v1 = a1 * sc;
        sv[wid*C_ + lane]      = v0;
        sv[wid*C_ + 32 + lane] = v1;
        float* vo = (vout_ext ? vout_ext : g_v) + ((size_t)(b0+wid)*N_ + n)*C_;
        vo[lane]      = v0;
        vo[32 + lane] = v1;
    }
    __syncthreads();

    // p[b][d] = sum_c W[d][c] * v[b][c]; thread = (bb = t>>7, dl = t&127), 2 d's each
    if (compute_p) {
        const int bb = t >> 7, dl = t & 127;
        const float4* sv4 = (const float4*)(sv + bb*C_);
        #pragma unroll
        for (int dd = 0; dd < 2; dd++) {
            const int d = dd*128 + dl;
            const float4* wr4 = (const float4*)sW + d*(WPAD/4);  // WPAD/4 = 17
            float acc = 0.f;
            #pragma unroll
            for (int c4 = 0; c4 < 16; c4++) {
                float4 w = wr4[c4];
                float4 v = sv4[c4];
                acc += w.x*v.x + w.y*v.y + w.z*v.z + w.w*v.w;
            }
            size_t o = ((size_t)(b0+bb)*N_ + n)*D_ + d;
            __nv_bfloat16 h = __float2bfloat16(acc);
            g_phi[o] = h;
            g_plo[o] = __float2bfloat16(acc - __bfloat162float(h));
        }
    }
}

// ---------------- fused routing pass (tensor cores) --------------------------
// grid = B_*CHUNKS (1024), 256 threads, 3 CTAs/SM. Reads fp32 x, splits on the fly.
__global__ __launch_bounds__(TPB, 3) void pass_kernel(const float* __restrict__ x, int first) {
    extern __shared__ char smc[];
    char* xh  = smc + O_XH;
    char* xl  = smc + O_XL;
    char* ph  = smc + O_PH;
    char* pl  = smc + O_PL;
    char* cth = smc + O_CTH;
    char* ctl = smc + O_CTL;
    float* cS = (float*)(smc + O_CS);   // aliases cth/ctl; live ranges disjoint

    const int t = threadIdx.x, wid = t >> 5, lane = t & 31;
    const int b  = blockIdx.x >> 5;
    const int ch = blockIdx.x & 31;
    const int s0 = ch * SCH;

    // load x tile fp32 and split-convert to bf16 hi/lo planes
    {
        const float4* xg = (const float4*)(x + ((size_t)(b*S_ + s0)) * D_);
        #pragma unroll
        for (int i = t; i < SCH*64; i += TPB) {   // 2048 float4
            int s = i >> 6, dq = i & 63;
            uint2 hh, ll;
            split4(xg[i], hh, ll);
            *(uint2*)(xh + s*XPB + dq*8) = hh;
            *(uint2*)(xl + s*XPB + dq*8) = ll;
        }
        const uint4* qh = (const uint4*)(g_phi + (size_t)b * N_ * D_);
        const uint4* ql = (const uint4*)(g_plo + (size_t)b * N_ * D_);
        #pragma unroll
        for (int i = t; i < N_*32; i += TPB) {
            int n = i >> 5, q = i & 31;
            *(uint4*)(ph + n*PPB + q*16) = qh[i];
            *(uint4*)(pl + n*PPB + q*16) = ql[i];
        }
    }
    __syncthreads();

    // phase 2: agree = X (32s x 256k) @ P^T -> warp tile m16(s) x n8(n), full K
    {
        const int pm = wid & 1, pn = wid >> 1;       // 2 x 4 warp grid
        const int s0w = pm * 16, n0w = pn * 8;
        const uint32_t aH = smem_u32(xh) + (s0w + (lane & 15))*XPB + (lane >> 4)*16;
        const uint32_t aL = smem_u32(xl) + (s0w + (lane & 15))*XPB + (lane >> 4)*16;
        const uint32_t bH = smem_u32(ph) + (n0w + (lane & 7))*PPB + ((lane >> 3) & 1)*16;
        const uint32_t bL = smem_u32(pl) + (n0w + (lane & 7))*PPB + ((lane >> 3) & 1)*16;
        float c1[4] = {0.f,0.f,0.f,0.f};
        float c2[4] = {0.f,0.f,0.f,0.f};
        float c3[4] = {0.f,0.f,0.f,0.f};
        #pragma unroll
        for (int k = 0; k < 16; k++) {
            uint32_t ah0,ah1,ah2,ah3, al0,al1,al2,al3, bh0,bh1, bl0,bl1;
            LDM_X4(ah0,ah1,ah2,ah3, aH + k*32);
            LDM_X4(al0,al1,al2,al3, aL + k*32);
            LDM_X2(bh0,bh1, bH + k*32);
            LDM_X2(bl0,bl1, bL + k*32);
            mma_bf16(c1, ah0,ah1,ah2,ah3, bh0,bh1);   // hi*hi
            mma_bf16(c2, ah0,ah1,ah2,ah3, bl0,bl1);   // hi*lo
            mma_bf16(c3, al0,al1,al2,al3, bh0,bh1);   // lo*hi
        }
        const int sr = s0w + (lane >> 2), nc = n0w + (lane & 3)*2;
        cS[sr*CPAD + nc]         = c1[0] + c2[0] + c3[0];
        cS[sr*CPAD + nc + 1]     = c1[1] + c2[1] + c3[1];
        cS[(sr+8)*CPAD + nc]     = c1[2] + c2[2] + c3[2];
        cS[(sr+8)*CPAD + nc + 1] = c1[3] + c2[3] + c3[3];
    }
    __syncthreads();

    // softmax over n per s-row, split read -> barrier -> compute+write (cS alias)
    {
        float lg[4];
        #pragma unroll
        for (int r = 0; r < 4; r++) {
            int s = wid*4 + r;
            lg[r] = cS[s*CPAD + lane];
            size_t li = ((size_t)b * S_ + s0 + s) * N_ + lane;
            if (first) g_logits[li] = lg[r];
            else       lg[r] += g_logits[li];
        }
        __syncthreads();
        #pragma unroll
        for (int r = 0; r < 4; r++) {
            int s = wid*4 + r;
            float v = lg[r];
            float mx = v;
            #pragma unroll
            for (int o = 16; o > 0; o >>= 1) mx = fmaxf(mx, __shfl_xor_sync(0xffffffffu, mx, o));
            float e = expf(v - mx);
            float sum = e;
            #pragma unroll
            for (int o = 16; o > 0; o >>= 1) sum += __shfl_xor_sync(0xffffffffu, sum, o);
            float cv = e / sum;
            __nv_bfloat16 hh = __float2bfloat16(cv);
            *(__nv_bfloat16*)(cth + lane*CTPB + s*2) = hh;
            *(__nv_bfloat16*)(ctl + lane*CTPB + s*2) =
                __float2bfloat16(cv - __bfloat162float(hh));
        }
    }
    __syncthreads();

    // phase 3: y = C^T (32n x 32k(s)) @ X (32s x 256d) -> warp m16(n) x 64d
    {
        const int wm = wid & 1, wd = wid >> 1;       // 2 x 4 warp grid
        const int n0w = wm * 16, d0w = wd * 64;
        const uint32_t aH = smem_u32(cth) + (n0w + (lane & 15))*CTPB + (lane >> 4)*16;
        const uint32_t aL = smem_u32(ctl) + (n0w + (lane & 15))*CTPB + (lane >> 4)*16;
        const int part  = lane >> 3;
        const int brow  = (part & 1)*8 + (lane & 7);
        const int bcolb = (part >> 1)*16;
        float acc[8][4];
        #pragma unroll
        for (int i = 0; i < 8; i++)
            #pragma unroll
            for (int j = 0; j < 4; j++) acc[i][j] = 0.f;

        #pragma unroll
        for (int ks = 0; ks < 2; ks++) {
            uint32_t ah0,ah1,ah2,ah3, al0,al1,al2,al3;
            LDM_X4(ah0,ah1,ah2,ah3, aH + ks*32);
            LDM_X4(al0,al1,al2,al3, aL + ks*32);
            #pragma unroll
            for (int j = 0; j < 4; j++) {
                const int dd = d0w + j*16;
                const uint32_t xb  = smem_u32(xh) + (ks*16 + brow)*XPB + dd*2 + bcolb;
                const uint32_t xlb = smem_u32(xl) + (ks*16 + brow)*XPB + dd*2 + bcolb;
                uint32_t bh0,bh1,bh2,bh3, bl0,bl1,bl2,bl3;
                LDM_X4T(bh0,bh1,bh2,bh3, xb);
                LDM_X4T(bl0,bl1,bl2,bl3, xlb);
                mma_bf16(acc[2*j],   ah0,ah1,ah2,ah3, bh0,bh1);
                mma_bf16(acc[2*j],   ah0,ah1,ah2,ah3, bl0,bl1);
                mma_bf16(acc[2*j],   al0,al1,al2,al3, bh0,bh1);
                mma_bf16(acc[2*j+1], ah0,ah1,ah2,ah3, bh2,bh3);
                mma_bf16(acc[2*j+1], ah0,ah1,ah2,ah3, bl2,bl3);
                mma_bf16(acc[2*j+1], al0,al1,al2,al3, bh2,bh3);
            }
        }
        float* yo = (first ? g_ya : g_yb) + (size_t)b * N_ * D_;
        const int nr = n0w + (lane >> 2);
        #pragma unroll
        for (int jj = 0; jj < 8; jj++) {
            int d = d0w + jj*8 + (lane & 3)*2;
            red_add_v2(&yo[nr*D_ + d],     acc[jj][0], acc[jj][1]);
            red_add_v2(&yo[(nr+8)*D_ + d], acc[jj][2], acc[jj][3]);
        }
    }
}

// ---------------- launch ----------------------------------------------------
extern "C" void kernel_launch(void* const* d_in, const int* in_sizes, int n_in,
                              void* d_out, int out_size) {
    (void)in_sizes; (void)n_in; (void)out_size;
    const float* x = (const float*)d_in[0];
    const float* W = (const float*)d_in[1];
    float* out = (float*)d_out;

    cudaFuncSetAttribute(capsule_kernel, cudaFuncAttributeMaxDynamicSharedMemorySize, CAPS_SMEM);
    cudaFuncSetAttribute(pass_kernel,    cudaFuncAttributeMaxDynamicSharedMemorySize, PASS_SMEM);

    reduce_x_kernel<<<B_*8, 256>>>(x);                 // y0 partials + zero ya/yb

    capsule_kernel<<<dim3(N_, B_/CB), CTPB_THREADS, CAPS_SMEM>>>(W, 0, nullptr, 1); // v0, p0
    pass_kernel<<<B_*CHUNKS, TPB, PASS_SMEM>>>(x, 1);                               // iter1
    capsule_kernel<<<dim3(N_, B_/CB), CTPB_THREADS, CAPS_SMEM>>>(W, 1, nullptr, 1); // v1, p1
    pass_kernel<<<B_*CHUNKS, TPB, PASS_SMEM>>>(x, 0);                               // iter2
    capsule_kernel<<<dim3(N_, B_/CB), CTPB_THREADS, CAPS_SMEM>>>(W, 2, out, 0);     // v2 -> out
}

// round 15
// speedup vs baseline: 1.0254x; 1.0254x over previous
#include <cuda_runtime.h>
#include <cuda_bf16.h>
#include <math.h>
#include <stdint.h>

// Problem constants
#define B_  32
#define S_  1024
#define D_  256
#define N_  32
#define C_  64
#define M_  (B_*S_)

// pass kernel tiling (tensor-core version)
#define SCH 32                // s-values per block
#define CHUNKS (S_/SCH)       // 32
#define TPB 256               // 8 warps
#define XPB 528               // x smem row pitch BYTES (264 bf16; 33 x 16B, odd)
#define PPB 528               // p smem row pitch bytes
#define CTPB 80               // cT row pitch bytes (40 bf16; 5 x 16B, odd)
#define CPAD 36               // agree fp32 row stride (floats)

// smem byte offsets; cS (4608 B) aliases cth+ctl (5120 B) — live ranges disjoint
#define O_XH  0
#define O_XL  (O_XH + SCH*XPB)       // 16896
#define O_PH  (O_XL + SCH*XPB)       // 33792
#define O_PL  (O_PH + N_*PPB)        // 50688
#define O_CS  (O_PL + N_*PPB)        // 67584
#define O_CTH O_CS                   // 67584 (alias)
#define O_CTL (O_CTH + N_*CTPB)      // 70144
#define PASS_SMEM (O_CTL + N_*CTPB)  // 72704 B -> 3 CTAs/SM (218112 total)

// capsule: 4 b's per block, 512 threads, grid (N_, B_/4) = 256 blocks
#define WPAD 68               // W smem row stride (floats); 17 float4/row
#define CB 4                  // b's per capsule block
#define CTPB_THREADS 512
// sW + sy + ss(8 d-halves) + sv
#define CAPS_SMEM ((D_*WPAD + CB*D_ + 8*CB*C_ + CB*C_) * 4)  // 82944 B

// ---------------- scratch (device globals; no runtime allocation) ----------
__device__ float          g_y0p[8*B_*D_];     // per-chunk partials of (1/N) sum_s x
__device__ float          g_ya[B_*N_*D_];     // y for iter1
__device__ float          g_yb[B_*N_*D_];     // y for iter2
__device__ float          g_v [B_*N_*C_];
__device__ float          g_logits[B_*S_*N_];
__device__ __nv_bfloat16  g_phi[B_*N_*D_];
__device__ __nv_bfloat16  g_plo[B_*N_*D_];

// ---------------- PTX helpers ----------------------------------------------
__device__ __forceinline__ uint32_t smem_u32(const void* p) {
    uint32_t a;
    asm("{ .reg .u64 t; cvta.to.shared.u64 t, %1; cvt.u32.u64 %0, t; }" : "=r"(a) : "l"(p));
    return a;
}
#define LDM_X4(r0,r1,r2,r3,a) \
    asm volatile("ldmatrix.sync.aligned.m8n8.x4.shared.b16 {%0,%1,%2,%3}, [%4];" \
        : "=r"(r0),"=r"(r1),"=r"(r2),"=r"(r3) : "r"(a))
#define LDM_X2(r0,r1,a) \
    asm volatile("ldmatrix.sync.aligned.m8n8.x2.shared.b16 {%0,%1}, [%2];" \
        : "=r"(r0),"=r"(r1) : "r"(a))
#define LDM_X4T(r0,r1,r2,r3,a) \
    asm volatile("ldmatrix.sync.aligned.m8n8.x4.trans.shared.b16 {%0,%1,%2,%3}, [%4];" \
        : "=r"(r0),"=r"(r1),"=r"(r2),"=r"(r3) : "r"(a))
__device__ __forceinline__ void mma_bf16(float* c, uint32_t a0, uint32_t a1, uint32_t a2,
                                         uint32_t a3, uint32_t b0, uint32_t b1) {
    asm volatile(
        "mma.sync.aligned.m16n8k16.row.col.f32.bf16.bf16.f32 "
        "{%0,%1,%2,%3}, {%4,%5,%6,%7}, {%8,%9}, {%0,%1,%2,%3};"
        : "+f"(c[0]), "+f"(c[1]), "+f"(c[2]), "+f"(c[3])
        : "r"(a0), "r"(a1), "r"(a2), "r"(a3), "r"(b0), "r"(b1));
}
__device__ __forceinline__ void red_add_v2(float* p, float a, float b) {
    asm volatile("red.global.add.v2.f32 [%0], {%1, %2};"
        :: "l"(__cvta_generic_to_global(p)), "f"(a), "f"(b) : "memory");
}

// split a float4 into hi/lo bf16x2-pairs (uint2 each)
__device__ __forceinline__ void split4(float4 v, uint2& hh, uint2& ll) {
    __nv_bfloat162 h01 = __float22bfloat162_rn(make_float2(v.x, v.y));
    __nv_bfloat162 h23 = __float22bfloat162_rn(make_float2(v.z, v.w));
    __nv_bfloat162 l01 = __float22bfloat162_rn(make_float2(
        v.x - __bfloat162float(h01.x), v.y - __bfloat162float(h01.y)));
    __nv_bfloat162 l23 = __float22bfloat162_rn(make_float2(
        v.z - __bfloat162float(h23.x), v.w - __bfloat162float(h23.y)));
    hh = make_uint2(*(uint32_t*)&h01, *(uint32_t*)&h23);
    ll = make_uint2(*(uint32_t*)&l01, *(uint32_t*)&l23);
}

// ---------------- y0 partials + ya/yb zeroing (read-only reduction) ---------
__global__ __launch_bounds__(256) void reduce_x_kernel(const float* __restrict__ x) {
    __shared__ float sred[256*4];
    const int b  = blockIdx.x >> 3;     // 32
    const int sg = blockIdx.x & 7;      // 8 groups x 128 s
    const int t  = threadIdx.x;
    const int q  = t & 63;              // d-quad: d = 4q
    const int rg = t >> 6;              // row-group 0..3
    const size_t rowbase = (size_t)b * S_ + sg * 128;

    {
        float4 z = make_float4(0.f, 0.f, 0.f, 0.f);
        ((float4*)g_ya)[blockIdx.x*256 + t] = z;
        ((float4*)g_yb)[blockIdx.x*256 + t] = z;
    }

    float4 a = make_float4(0.f, 0.f, 0.f, 0.f);
    #pragma unroll 8
    for (int it = 0; it < 32; it++) {
        const int s = it*4 + rg;
        const float4 v = *(const float4*)(x + (rowbase + s) * D_ + 4*q);
        a.x += v.x; a.y += v.y; a.z += v.z; a.w += v.w;
    }
    *(float4*)&sred[t*4] = a;
    __syncthreads();
    if (t < 64) {
        float4 r0 = *(const float4*)&sred[t*4];
        float4 r1 = *(const float4*)&sred[(t+64)*4];
        float4 r2 = *(const float4*)&sred[(t+128)*4];
        float4 r3 = *(const float4*)&sred[(t+192)*4];
        const float sc = 1.0f / (float)N_;
        float4 o = make_float4((r0.x+r1.x+r2.x+r3.x)*sc, (r0.y+r1.y+r2.y+r3.y)*sc,
                               (r0.z+r1.z+r2.z+r3.z)*sc, (r0.w+r1.w+r2.w+r3.w)*sc);
        *(float4*)&g_y0p[(sg*B_ + b)*D_ + 4*t] = o;
    }
}

// ---------------- capsule: s = y@W, v = squash(s), p = W@v (split-bf16) -----
// grid (N_, B_/CB) = (32, 8), 512 threads.
__global__ __launch_bounds__(CTPB_THREADS) void capsule_kernel(
        const float* __restrict__ W, int ysel, float* __restrict__ vout_ext, int compute_p) {
    extern __shared__ float sm[];
    float* sW = sm;                 // [D_][WPAD]
    float* sy = sW + D_*WPAD;       // [CB][D_]
    float* ss = sy + CB*D_;         // [8][CB][C_]  (eight 32-d halves)
    float* sv = ss + 8*CB*C_;       // [CB][C_]

    const int n  = blockIdx.x;
    const int b0 = blockIdx.y * CB;
    const int t  = threadIdx.x;

    // W[n] load: 4096 float4 via LDG.128 -> STS.128, 8 per thread
    {
        const float4* Wn4 = (const float4*)(W + (size_t)n * D_ * C_);
        #pragma unroll
        for (int k = 0; k < 8; k += 4) {
            int j0 = t + (k+0)*512, j1 = t + (k+1)*512, j2 = t + (k+2)*512, j3 = t + (k+3)*512;
            float4 w0 = Wn4[j0];
            float4 w1 = Wn4[j1];
            float4 w2 = Wn4[j2];
            float4 w3 = Wn4[j3];
            *(float4*)&sW[(j0>>4)*WPAD + 4*(j0&15)] = w0;
            *(float4*)&sW[(j1>>4)*WPAD + 4*(j1&15)] = w1;
            *(float4*)&sW[(j2>>4)*WPAD + 4*(j2&15)] = w2;
            *(float4*)&sW[(j3>>4)*WPAD + 4*(j3&15)] = w3;
        }
    }
    // y rows for CB b's: CB*D_/512 = 2 per thread
    #pragma unroll
    for (int k = 0; k < CB*D_/CTPB_THREADS; k++) {
        int i = t + k*CTPB_THREADS;
        int bb = i >> 8, d = i & 255;
        if (ysel == 0) {
            float a = 0.f;
            #pragma unroll
            for (int p8 = 0; p8 < 8; p8++) a += g_y0p[(p8*B_ + b0+bb)*D_ + d];
            sy[bb*D_ + d] = a;
        } else {
            const float* ysrc = (ysel == 1) ? g_ya : g_yb;
            sy[bb*D_ + d] = ysrc[((size_t)(b0+bb)*N_ + n)*D_ + d];
        }
    }
    __syncthreads();

    // s[b][c] = sum_d y[b][d] * W[d][c]
    // thread tile: c-quad c4 = t&15 (c = 4*c4), bb = (t>>4)&3, half = t>>6 (32 d's)
    // W read as float4 rows (LDS.128), y as scalar broadcast: 40 LDS/thread.
    {
        const int c4 = t & 15, bb = (t >> 4) & 3, half = t >> 6;
        const float* yr = sy + bb*D_ + half*32;
        const float4* w4 = (const float4*)sW + (half*32)*(WPAD/4) + c4;  // WPAD/4 = 17
        float4 acc = make_float4(0.f, 0.f, 0.f, 0.f);
        #pragma unroll
        for (int d = 0; d < 32; d++) {
            float4 w = w4[d*17];
            float yv = yr[d];
            acc.x += yv * w.x; acc.y += yv * w.y;
            acc.z += yv * w.z; acc.w += yv * w.w;
        }
        *(float4*)&ss[half*CB*C_ + bb*C_ + 4*c4] = acc;
    }
    __syncthreads();

    // squash: warps 0..CB-1, warp wid handles b = b0+wid (combines 8 d-halves)
    const int wid = t >> 5, lane = t & 31;
    if (wid < CB) {
        float a0 = 0.f, a1 = 0.f;
        #pragma unroll
        for (int h = 0; h < 8; h++) {
            a0 += ss[h*CB*C_ + wid*C_ + lane];
            a1 += ss[h*CB*C_ + wid*C_ + 32 + lane];
        }
        float sq = a0*a0 + a1*a1;
        #pragma unroll
        for (int o = 16; o > 0; o >>= 1) sq += __shfl_xor_sync(0xffffffffu, sq, o);
        float sc = (sq / (1.f + sq)) * rsqrtf(sq + 1e-8f);
        float v0 = a0 * sc, v1 = a1 * sc;
        sv[wid*C_ + lane]      = v0;
        sv[wid*C_ + 32 + lane] = v1;
        float* vo = (vout_ext ? vout_ext : g_v) + ((size_t)(b0+wid)*N_ + n)*C_;
        vo[lane]      = v0;
        vo[32 + lane] = v1;
    }
    __syncthreads();

    // p[b][d] = sum_c W[d][c] * v[b][c]; thread = (bb = t>>7, dl = t&127), 2 d's each
    if (compute_p) {
        const int bb = t >> 7, dl = t & 127;
        const float4* sv4 = (const float4*)(sv + bb*C_);
        #pragma unroll
        for (int dd = 0; dd < 2; dd++) {
            const int d = dd*128 + dl;
            const float4* wr4 = (const float4*)sW + d*(WPAD/4);
            float acc = 0.f;
            #pragma unroll
            for (int c4 = 0; c4 < 16; c4++) {
                float4 w = wr4[c4];
                float4 v = sv4[c4];
                acc += w.x*v.x + w.y*v.y + w.z*v.z + w.w*v.w;
            }
            size_t o = ((size_t)(b0+bb)*N_ + n)*D_ + d;
            __nv_bfloat16 h = __float2bfloat16(acc);
            g_phi[o] = h;
            g_plo[o] = __float2bfloat16(acc - __bfloat162float(h));
        }
    }
}

// ---------------- fused routing pass (tensor cores) --------------------------
// grid = B_*CHUNKS (1024), 256 threads, 3 CTAs/SM. Reads fp32 x, splits on the fly.
__global__ __launch_bounds__(TPB, 3) void pass_kernel(const float* __restrict__ x, int first) {
    extern __shared__ char smc[];
    char* xh  = smc + O_XH;
    char* xl  = smc + O_XL;
    char* ph  = smc + O_PH;
    char* pl  = smc + O_PL;
    char* cth = smc + O_CTH;
    char* ctl = smc + O_CTL;
    float* cS = (float*)(smc + O_CS);   // aliases cth/ctl; live ranges disjoint

    const int t = threadIdx.x, wid = t >> 5, lane = t & 31;
    const int b  = blockIdx.x >> 5;
    const int ch = blockIdx.x & 31;
    const int s0 = ch * SCH;

    // load x tile fp32 and split-convert to bf16 hi/lo planes
    {
        const float4* xg = (const float4*)(x + ((size_t)(b*S_ + s0)) * D_);
        #pragma unroll
        for (int i = t; i < SCH*64; i += TPB) {   // 2048 float4
            int s = i >> 6, dq = i & 63;
            uint2 hh, ll;
            split4(xg[i], hh, ll);
            *(uint2*)(xh + s*XPB + dq*8) = hh;
            *(uint2*)(xl + s*XPB + dq*8) = ll;
        }
        const uint4* qh = (const uint4*)(g_phi + (size_t)b * N_ * D_);
        const uint4* ql = (const uint4*)(g_plo + (size_t)b * N_ * D_);
        #pragma unroll
        for (int i = t; i < N_*32; i += TPB) {
            int n = i >> 5, q = i & 31;
            *(uint4*)(ph + n*PPB + q*16) = qh[i];
            *(uint4*)(pl + n*PPB + q*16) = ql[i];
        }
    }
    __syncthreads();

    // phase 2: agree = X (32s x 256k) @ P^T -> warp tile m16(s) x n8(n), full K
    {
        const int pm = wid & 1, pn = wid >> 1;       // 2 x 4 warp grid
        const int s0w = pm * 16, n0w = pn * 8;
        const uint32_t aH = smem_u32(xh) + (s0w + (lane & 15))*XPB + (lane >> 4)*16;
        const uint32_t aL = smem_u32(xl) + (s0w + (lane & 15))*XPB + (lane >> 4)*16;
        const uint32_t bH = smem_u32(ph) + (n0w + (lane & 7))*PPB + ((lane >> 3) & 1)*16;
        const uint32_t bL = smem_u32(pl) + (n0w + (lane & 7))*PPB + ((lane >> 3) & 1)*16;
        float c1[4] = {0.f,0.f,0.f,0.f};
        float c2[4] = {0.f,0.f,0.f,0.f};
        float c3[4] = {0.f,0.f,0.f,0.f};
        #pragma unroll
        for (int k = 0; k < 16; k++) {
            uint32_t ah0,ah1,ah2,ah3, al0,al1,al2,al3, bh0,bh1, bl0,bl1;
            LDM_X4(ah0,ah1,ah2,ah3, aH + k*32);
            LDM_X4(al0,al1,al2,al3, aL + k*32);
            LDM_X2(bh0,bh1, bH + k*32);
            LDM_X2(bl0,bl1, bL + k*32);
            mma_bf16(c1, ah0,ah1,ah2,ah3, bh0,bh1);   // hi*hi
            mma_bf16(c2, ah0,ah1,ah2,ah3, bl0,bl1);   // hi*lo
            mma_bf16(c3, al0,al1,al2,al3, bh0,bh1);   // lo*hi
        }
        const int sr = s0w + (lane >> 2), nc = n0w + (lane & 3)*2;
        cS[sr*CPAD + nc]         = c1[0] + c2[0] + c3[0];
        cS[sr*CPAD + nc + 1]     = c1[1] + c2[1] + c3[1];
        cS[(sr+8)*CPAD + nc]     = c1[2] + c2[2] + c3[2];
        cS[(sr+8)*CPAD + nc + 1] = c1[3] + c2[3] + c3[3];
    }
    __syncthreads();

    // softmax over n per s-row, split read -> barrier -> compute+write (cS alias)
    {
        float lg[4];
        #pragma unroll
        for (int r = 0; r < 4; r++) {
            int s = wid*4 + r;
            lg[r] = cS[s*CPAD + lane];
            size_t li = ((size_t)b * S_ + s0 + s) * N_ + lane;
            if (first) g_logits[li] = lg[r];
            else       lg[r] += g_logits[li];
        }
        __syncthreads();
        #pragma unroll
        for (int r = 0; r < 4; r++) {
            int s = wid*4 + r;
            float v = lg[r];
            float mx = v;
            #pragma unroll
            for (int o = 16; o > 0; o >>= 1) mx = fmaxf(mx, __shfl_xor_sync(0xffffffffu, mx, o));
            float e = expf(v - mx);
            float sum = e;
            #pragma unroll
            for (int o = 16; o > 0; o >>= 1) sum += __shfl_xor_sync(0xffffffffu, sum, o);
            float cv = e / sum;
            __nv_bfloat16 hh = __float2bfloat16(cv);
            *(__nv_bfloat16*)(cth + lane*CTPB + s*2) = hh;
            *(__nv_bfloat16*)(ctl + lane*CTPB + s*2) =
                __float2bfloat16(cv - __bfloat162float(hh));
        }
    }
    __syncthreads();

    // phase 3: y = C^T (32n x 32k(s)) @ X (32s x 256d) -> warp m16(n) x 64d
    {
        const int wm = wid & 1, wd = wid >> 1;       // 2 x 4 warp grid
        const int n0w = wm * 16, d0w = wd * 64;
        const uint32_t aH = smem_u32(cth) + (n0w + (lane & 15))*CTPB + (lane >> 4)*16;
        const uint32_t aL = smem_u32(ctl) + (n0w + (lane & 15))*CTPB + (lane >> 4)*16;
        const int part  = lane >> 3;
        const int brow  = (part & 1)*8 + (lane & 7);
        const int bcolb = (part >> 1)*16;
        float acc[8][4];
        #pragma unroll
        for (int i = 0; i < 8; i++)
            #pragma unroll
            for (int j = 0; j < 4; j++) acc[i][j] = 0.f;

        #pragma unroll
        for (int ks = 0; ks < 2; ks++) {
            uint32_t ah0,ah1,ah2,ah3, al0,al1,al2,al3;
            LDM_X4(ah0,ah1,ah2,ah3, aH + ks*32);
            LDM_X4(al0,al1,al2,al3, aL + ks*32);
            #pragma unroll
            for (int j = 0; j < 4; j++) {
                const int dd = d0w + j*16;
                const uint32_t xb  = smem_u32(xh) + (ks*16 + brow)*XPB + dd*2 + bcolb;
                const uint32_t xlb = smem_u32(xl) + (ks*16 + brow)*XPB + dd*2 + bcolb;
                uint32_t bh0,bh1,bh2,bh3, bl0,bl1,bl2,bl3;
                LDM_X4T(bh0,bh1,bh2,bh3, xb);
                LDM_X4T(bl0,bl1,bl2,bl3, xlb);
                mma_bf16(acc[2*j],   ah0,ah1,ah2,ah3, bh0,bh1);
                mma_bf16(acc[2*j],   ah0,ah1,ah2,ah3, bl0,bl1);
                mma_bf16(acc[2*j],   al0,al1,al2,al3, bh0,bh1);
                mma_bf16(acc[2*j+1], ah0,ah1,ah2,ah3, bh2,bh3);
                mma_bf16(acc[2*j+1], ah0,ah1,ah2,ah3, bl2,bl3);
                mma_bf16(acc[2*j+1], al0,al1,al2,al3, bh2,bh3);
            }
        }
        float* yo = (first ? g_ya : g_yb) + (size_t)b * N_ * D_;
        const int nr = n0w + (lane >> 2);
        #pragma unroll
        for (int jj = 0; jj < 8; jj++) {
            int d = d0w + jj*8 + (lane & 3)*2;
            red_add_v2(&yo[nr*D_ + d],     acc[jj][0], acc[jj][1]);
            red_add_v2(&yo[(nr+8)*D_ + d], acc[jj][2], acc[jj][3]);
        }
    }
}

// ---------------- launch ----------------------------------------------------
extern "C" void kernel_launch(void* const* d_in, const int* in_sizes, int n_in,
                              void* d_out, int out_size) {
    (void)in_sizes; (void)n_in; (void)out_size;
    const float* x = (const float*)d_in[0];
    const float* W = (const float*)d_in[1];
    float* out = (float*)d_out;

    cudaFuncSetAttribute(capsule_kernel, cudaFuncAttributeMaxDynamicSharedMemorySize, CAPS_SMEM);
    cudaFuncSetAttribute(pass_kernel,    cudaFuncAttributeMaxDynamicSharedMemorySize, PASS_SMEM);

    reduce_x_kernel<<<B_*8, 256>>>(x);                 // y0 partials + zero ya/yb

    capsule_kernel<<<dim3(N_, B_/CB), CTPB_THREADS, CAPS_SMEM>>>(W, 0, nullptr, 1); // v0, p0
    pass_kernel<<<B_*CHUNKS, TPB, PASS_SMEM>>>(x, 1);                               // iter1
    capsule_kernel<<<dim3(N_, B_/CB), CTPB_THREADS, CAPS_SMEM>>>(W, 1, nullptr, 1); // v1, p1
    pass_kernel<<<B_*CHUNKS, TPB, PASS_SMEM>>>(x, 0);                               // iter2
    capsule_kernel<<<dim3(N_, B_/CB), CTPB_THREADS, CAPS_SMEM>>>(W, 2, out, 0);     // v2 -> out
}

// round 16
// speedup vs baseline: 1.0521x; 1.0261x over previous
#include <cuda_runtime.h>
#include <cuda_bf16.h>
#include <math.h>
#include <stdint.h>

// Problem constants
#define B_  32
#define S_  1024
#define D_  256
#define N_  32
#define C_  64
#define M_  (B_*S_)

// pass kernel tiling (tensor-core version)
#define SCH 32                // s-values per block
#define CHUNKS (S_/SCH)       // 32
#define TPB 256               // 8 warps
#define XPB 528               // x smem row pitch BYTES (264 bf16; 33 x 16B, odd)
#define PPB 528               // p smem row pitch bytes
#define CTPB 80               // cT row pitch bytes (40 bf16; 5 x 16B, odd)
#define CPAD 36               // agree fp32 row stride (floats)

// smem byte offsets; cS (4608 B) aliases cth+ctl (5120 B) — live ranges disjoint
#define O_XH  0
#define O_XL  (O_XH + SCH*XPB)       // 16896
#define O_PH  (O_XL + SCH*XPB)       // 33792
#define O_PL  (O_PH + N_*PPB)        // 50688
#define O_CS  (O_PL + N_*PPB)        // 67584
#define O_CTH O_CS                   // 67584 (alias)
#define O_CTL (O_CTH + N_*CTPB)      // 70144
#define PASS_SMEM (O_CTL + N_*CTPB)  // 72704 B -> 3 CTAs/SM (218112 total)

// capsule: 8 b's per block, 512 threads, grid (N_, B_/8) = 128 blocks (ONE wave)
#define WPAD 68               // W smem row stride (floats); 17 float4/row
#define CB 8                  // b's per capsule block
#define CTPB_THREADS 512
// sW + sy + ss(4 d-quarters) + sv
#define CAPS_SMEM ((D_*WPAD + CB*D_ + 4*CB*C_ + CB*C_) * 4)  // 96256 B

// ---------------- scratch (device globals; no runtime allocation) ----------
__device__ float          g_y0p[8*B_*D_];     // per-chunk partials of (1/N) sum_s x
__device__ float          g_ya[B_*N_*D_];     // y for iter1
__device__ float          g_yb[B_*N_*D_];     // y for iter2
__device__ float          g_v [B_*N_*C_];
__device__ float          g_logits[B_*S_*N_];
__device__ __nv_bfloat16  g_phi[B_*N_*D_];
__device__ __nv_bfloat16  g_plo[B_*N_*D_];

// ---------------- PTX helpers ----------------------------------------------
__device__ __forceinline__ uint32_t smem_u32(const void* p) {
    uint32_t a;
    asm("{ .reg .u64 t; cvta.to.shared.u64 t, %1; cvt.u32.u64 %0, t; }" : "=r"(a) : "l"(p));
    return a;
}
#define LDM_X4(r0,r1,r2,r3,a) \
    asm volatile("ldmatrix.sync.aligned.m8n8.x4.shared.b16 {%0,%1,%2,%3}, [%4];" \
        : "=r"(r0),"=r"(r1),"=r"(r2),"=r"(r3) : "r"(a))
#define LDM_X2(r0,r1,a) \
    asm volatile("ldmatrix.sync.aligned.m8n8.x2.shared.b16 {%0,%1}, [%2];" \
        : "=r"(r0),"=r"(r1) : "r"(a))
#define LDM_X4T(r0,r1,r2,r3,a) \
    asm volatile("ldmatrix.sync.aligned.m8n8.x4.trans.shared.b16 {%0,%1,%2,%3}, [%4];" \
        : "=r"(r0),"=r"(r1),"=r"(r2),"=r"(r3) : "r"(a))
__device__ __forceinline__ void mma_bf16(float* c, uint32_t a0, uint32_t a1, uint32_t a2,
                                         uint32_t a3, uint32_t b0, uint32_t b1) {
    asm volatile(
        "mma.sync.aligned.m16n8k16.row.col.f32.bf16.bf16.f32 "
        "{%0,%1,%2,%3}, {%4,%5,%6,%7}, {%8,%9}, {%0,%1,%2,%3};"
        : "+f"(c[0]), "+f"(c[1]), "+f"(c[2]), "+f"(c[3])
        : "r"(a0), "r"(a1), "r"(a2), "r"(a3), "r"(b0), "r"(b1));
}
__device__ __forceinline__ void red_add_v2(float* p, float a, float b) {
    asm volatile("red.global.add.v2.f32 [%0], {%1, %2};"
        :: "l"(__cvta_generic_to_global(p)), "f"(a), "f"(b) : "memory");
}

// split a float4 into hi/lo bf16x2-pairs (uint2 each)
__device__ __forceinline__ void split4(float4 v, uint2& hh, uint2& ll) {
    __nv_bfloat162 h01 = __float22bfloat162_rn(make_float2(v.x, v.y));
    __nv_bfloat162 h23 = __float22bfloat162_rn(make_float2(v.z, v.w));
    __nv_bfloat162 l01 = __float22bfloat162_rn(make_float2(
        v.x - __bfloat162float(h01.x), v.y - __bfloat162float(h01.y)));
    __nv_bfloat162 l23 = __float22bfloat162_rn(make_float2(
        v.z - __bfloat162float(h23.x), v.w - __bfloat162float(h23.y)));
    hh = make_uint2(*(uint32_t*)&h01, *(uint32_t*)&h23);
    ll = make_uint2(*(uint32_t*)&l01, *(uint32_t*)&l23);
}

// ---------------- y0 partials + ya/yb zeroing (read-only reduction) ---------
__global__ __launch_bounds__(256) void reduce_x_kernel(const float* __restrict__ x) {
    __shared__ float sred[256*4];
    const int b  = blockIdx.x >> 3;     // 32
    const int sg = blockIdx.x & 7;      // 8 groups x 128 s
    const int t  = threadIdx.x;
    const int q  = t & 63;              // d-quad: d = 4q
    const int rg = t >> 6;              // row-group 0..3
    const size_t rowbase = (size_t)b * S_ + sg * 128;

    {
        float4 z = make_float4(0.f, 0.f, 0.f, 0.f);
        ((float4*)g_ya)[blockIdx.x*256 + t] = z;
        ((float4*)g_yb)[blockIdx.x*256 + t] = z;
    }

    float4 a = make_float4(0.f, 0.f, 0.f, 0.f);
    #pragma unroll 8
    for (int it = 0; it < 32; it++) {
        const int s = it*4 + rg;
        const float4 v = *(const float4*)(x + (rowbase + s) * D_ + 4*q);
        a.x += v.x; a.y += v.y; a.z += v.z; a.w += v.w;
    }
    *(float4*)&sred[t*4] = a;
    __syncthreads();
    if (t < 64) {
        float4 r0 = *(const float4*)&sred[t*4];
        float4 r1 = *(const float4*)&sred[(t+64)*4];
        float4 r2 = *(const float4*)&sred[(t+128)*4];
        float4 r3 = *(const float4*)&sred[(t+192)*4];
        const float sc = 1.0f / (float)N_;
        float4 o = make_float4((r0.x+r1.x+r2.x+r3.x)*sc, (r0.y+r1.y+r2.y+r3.y)*sc,
                               (r0.z+r1.z+r2.z+r3.z)*sc, (r0.w+r1.w+r2.w+r3.w)*sc);
        *(float4*)&g_y0p[(sg*B_ + b)*D_ + 4*t] = o;
    }
}

// ---------------- capsule: s = y@W, v = squash(s), p = W@v (split-bf16) -----
// grid (N_, B_/CB) = (32, 4) = 128 blocks -> one block per SM, single wave.
__global__ __launch_bounds__(CTPB_THREADS) void capsule_kernel(
        const float* __restrict__ W, int ysel, float* __restrict__ vout_ext, int compute_p) {
    extern __shared__ float sm[];
    float* sW = sm;                 // [D_][WPAD]
    float* sy = sW + D_*WPAD;       // [CB][D_]
    float* ss = sy + CB*D_;         // [4][CB][C_]  (four 64-d quarters)
    float* sv = ss + 4*CB*C_;       // [CB][C_]

    const int n  = blockIdx.x;
    const int b0 = blockIdx.y * CB;
    const int t  = threadIdx.x;

    // W[n] load: 4096 float4 via LDG.128 -> STS.128, 8 per thread
    {
        const float4* Wn4 = (const float4*)(W + (size_t)n * D_ * C_);
        #pragma unroll
        for (int k = 0; k < 8; k += 4) {
            int j0 = t + (k+0)*512, j1 = t + (k+1)*512, j2 = t + (k+2)*512, j3 = t + (k+3)*512;
            float4 w0 = Wn4[j0];
            float4 w1 = Wn4[j1];
            float4 w2 = Wn4[j2];
            float4 w3 = Wn4[j3];
            *(float4*)&sW[(j0>>4)*WPAD + 4*(j0&15)] = w0;
            *(float4*)&sW[(j1>>4)*WPAD + 4*(j1&15)] = w1;
            *(float4*)&sW[(j2>>4)*WPAD + 4*(j2&15)] = w2;
            *(float4*)&sW[(j3>>4)*WPAD + 4*(j3&15)] = w3;
        }
    }
    // y rows for CB b's: CB*D_/512 = 4 per thread
    #pragma unroll
    for (int k = 0; k < CB*D_/CTPB_THREADS; k++) {
        int i = t + k*CTPB_THREADS;
        int bb = i >> 8, d = i & 255;
        if (ysel == 0) {
            float a = 0.f;
            #pragma unroll
            for (int p8 = 0; p8 < 8; p8++) a += g_y0p[(p8*B_ + b0+bb)*D_ + d];
            sy[bb*D_ + d] = a;
        } else {
            const float* ysrc = (ysel == 1) ? g_ya : g_yb;
            sy[bb*D_ + d] = ysrc[((size_t)(b0+bb)*N_ + n)*D_ + d];
        }
    }
    __syncthreads();

    // s[b][c] = sum_d y[b][d] * W[d][c]
    // thread tile: c-quad c4 = t&15, bb = (t>>4)&7, quarter = t>>7 (64 d's)
    {
        const int c4 = t & 15, bb = (t >> 4) & 7, quarter = t >> 7;
        const float* yr = sy + bb*D_ + quarter*64;
        const float4* w4 = (const float4*)sW + (quarter*64)*(WPAD/4) + c4;  // WPAD/4 = 17
        float4 acc = make_float4(0.f, 0.f, 0.f, 0.f);
        #pragma unroll
        for (int d = 0; d < 64; d++) {
            float4 w = w4[d*17];
            float yv = yr[d];
            acc.x += yv * w.x; acc.y += yv * w.y;
            acc.z += yv * w.z; acc.w += yv * w.w;
        }
        *(float4*)&ss[quarter*CB*C_ + bb*C_ + 4*c4] = acc;
    }
    __syncthreads();

    // squash: warps 0..CB-1, warp wid handles b = b0+wid (combines 4 d-quarters)
    const int wid = t >> 5, lane = t & 31;
    if (wid < CB) {
        float a0 = 0.f, a1 = 0.f;
        #pragma unroll
        for (int h = 0; h < 4; h++) {
            a0 += ss[h*CB*C_ + wid*C_ + lane];
            a1 += ss[h*CB*C_ + wid*C_ + 32 + lane];
        }
        float sq = a0*a0 + a1*a1;
        #pragma unroll
        for (int o = 16; o > 0; o >>= 1) sq += __shfl_xor_sync(0xffffffffu, sq, o);
        float sc = (sq / (1.f + sq)) * rsqrtf(sq + 1e-8f);
        float v0 = a0 * sc, v1 = a1 * sc;
        sv[wid*C_ + lane]      = v0;
        sv[wid*C_ + 32 + lane] = v1;
        float* vo = (vout_ext ? vout_ext : g_v) + ((size_t)(b0+wid)*N_ + n)*C_;
        vo[lane]      = v0;
        vo[32 + lane] = v1;
    }
    __syncthreads();

    // p[b][d] = sum_c W[d][c] * v[b][c]; thread = (bb = t>>6, dl = t&63), 4 d's each
    if (compute_p) {
        const int bb = t >> 6, dl = t & 63;
        const float4* sv4 = (const float4*)(sv + bb*C_);
        #pragma unroll
        for (int dd = 0; dd < 4; dd++) {
            const int d = dd*64 + dl;
            const float4* wr4 = (const float4*)sW + d*(WPAD/4);
            float acc = 0.f;
            #pragma unroll
            for (int c4 = 0; c4 < 16; c4++) {
                float4 w = wr4[c4];
                float4 v = sv4[c4];
                acc += w.x*v.x + w.y*v.y + w.z*v.z + w.w*v.w;
            }
            size_t o = ((size_t)(b0+bb)*N_ + n)*D_ + d;
            __nv_bfloat16 h = __float2bfloat16(acc);
            g_phi[o] = h;
            g_plo[o] = __float2bfloat16(acc - __bfloat162float(h));
        }
    }
}

// ---------------- fused routing pass (tensor cores) --------------------------
// grid = B_*CHUNKS (1024), 256 threads, 3 CTAs/SM. Reads fp32 x, splits on the fly.
__global__ __launch_bounds__(TPB, 3) void pass_kernel(const float* __restrict__ x, int first) {
    extern __shared__ char smc[];
    char* xh  = smc + O_XH;
    char* xl  = smc + O_XL;
    char* ph  = smc + O_PH;
    char* pl  = smc + O_PL;
    char* cth = smc + O_CTH;
    char* ctl = smc + O_CTL;
    float* cS = (float*)(smc + O_CS);   // aliases cth/ctl; live ranges disjoint

    const int t = threadIdx.x, wid = t >> 5, lane = t & 31;
    const int b  = blockIdx.x >> 5;
    const int ch = blockIdx.x & 31;
    const int s0 = ch * SCH;

    // load x tile fp32 and split-convert to bf16 hi/lo planes
    {
        const float4* xg = (const float4*)(x + ((size_t)(b*S_ + s0)) * D_);
        #pragma unroll
        for (int i = t; i < SCH*64; i += TPB) {   // 2048 float4
            int s = i >> 6, dq = i & 63;
            uint2 hh, ll;
            split4(xg[i], hh, ll);
            *(uint2*)(xh + s*XPB + dq*8) = hh;
            *(uint2*)(xl + s*XPB + dq*8) = ll;
        }
        const uint4* qh = (const uint4*)(g_phi + (size_t)b * N_ * D_);
        const uint4* ql = (const uint4*)(g_plo + (size_t)b * N_ * D_);
        #pragma unroll
        for (int i = t; i < N_*32; i += TPB) {
            int n = i >> 5, q = i & 31;
            *(uint4*)(ph + n*PPB + q*16) = qh[i];
            *(uint4*)(pl + n*PPB + q*16) = ql[i];
        }
    }
    __syncthreads();

    // phase 2: agree = X (32s x 256k) @ P^T -> warp tile m16(s) x n8(n), full K
    {
        const int pm = wid & 1, pn = wid >> 1;       // 2 x 4 warp grid
        const int s0w = pm * 16, n0w = pn * 8;
        const uint32_t aH = smem_u32(xh) + (s0w + (lane & 15))*XPB + (lane >> 4)*16;
        const uint32_t aL = smem_u32(xl) + (s0w + (lane & 15))*XPB + (lane >> 4)*16;
        const uint32_t bH = smem_u32(ph) + (n0w + (lane & 7))*PPB + ((lane >> 3) & 1)*16;
        const uint32_t bL = smem_u32(pl) + (n0w + (lane & 7))*PPB + ((lane >> 3) & 1)*16;
        float c1[4] = {0.f,0.f,0.f,0.f};
        float c2[4] = {0.f,0.f,0.f,0.f};
        float c3[4] = {0.f,0.f,0.f,0.f};
        #pragma unroll
        for (int k = 0; k < 16; k++) {
            uint32_t ah0,ah1,ah2,ah3, al0,al1,al2,al3, bh0,bh1, bl0,bl1;
            LDM_X4(ah0,ah1,ah2,ah3, aH + k*32);
            LDM_X4(al0,al1,al2,al3, aL + k*32);
            LDM_X2(bh0,bh1, bH + k*32);
            LDM_X2(bl0,bl1, bL + k*32);
            mma_bf16(c1, ah0,ah1,ah2,ah3, bh0,bh1);   // hi*hi
            mma_bf16(c2, ah0,ah1,ah2,ah3, bl0,bl1);   // hi*lo
            mma_bf16(c3, al0,al1,al2,al3, bh0,bh1);   // lo*hi
        }
        const int sr = s0w + (lane >> 2), nc = n0w + (lane & 3)*2;
        cS[sr*CPAD + nc]         = c1[0] + c2[0] + c3[0];
        cS[sr*CPAD + nc + 1]     = c1[1] + c2[1] + c3[1];
        cS[(sr+8)*CPAD + nc]     = c1[2] + c2[2] + c3[2];
        cS[(sr+8)*CPAD + nc + 1] = c1[3] + c2[3] + c3[3];
    }
    __syncthreads();

    // softmax over n per s-row, split read -> barrier -> compute+write (cS alias)
    {
        float lg[4];
        #pragma unroll
        for (int r = 0; r < 4; r++) {
            int s = wid*4 + r;
            lg[r] = cS[s*CPAD + lane];
            size_t li = ((size_t)b * S_ + s0 + s) * N_ + lane;
            if (first) g_logits[li] = lg[r];
            else       lg[r] += g_logits[li];
        }
        __syncthreads();
        #pragma unroll
        for (int r = 0; r < 4; r++) {
            int s = wid*4 + r;
            float v = lg[r];
            float mx = v;
            #pragma unroll
            for (int o = 16; o > 0; o >>= 1) mx = fmaxf(mx, __shfl_xor_sync(0xffffffffu, mx, o));
            float e = expf(v - mx);
            float sum = e;
            #pragma unroll
            for (int o = 16; o > 0; o >>= 1) sum += __shfl_xor_sync(0xffffffffu, sum, o);
            float cv = e / sum;
            __nv_bfloat16 hh = __float2bfloat16(cv);
            *(__nv_bfloat16*)(cth + lane*CTPB + s*2) = hh;
            *(__nv_bfloat16*)(ctl + lane*CTPB + s*2) =
                __float2bfloat16(cv - __bfloat162float(hh));
        }
    }
    __syncthreads();

    // phase 3: y = C^T (32n x 32k(s)) @ X (32s x 256d) -> warp m16(n) x 64d
    {
        const int wm = wid & 1, wd = wid >> 1;       // 2 x 4 warp grid
        const int n0w = wm * 16, d0w = wd * 64;
        const uint32_t aH = smem_u32(cth) + (n0w + (lane & 15))*CTPB + (lane >> 4)*16;
        const uint32_t aL = smem_u32(ctl) + (n0w + (lane & 15))*CTPB + (lane >> 4)*16;
        const int part  = lane >> 3;
        const int brow  = (part & 1)*8 + (lane & 7);
        const int bcolb = (part >> 1)*16;
        float acc[8][4];
        #pragma unroll
        for (int i = 0; i < 8; i++)
            #pragma unroll
            for (int j = 0; j < 4; j++) acc[i][j] = 0.f;

        #pragma unroll
        for (int ks = 0; ks < 2; ks++) {
            uint32_t ah0,ah1,ah2,ah3, al0,al1,al2,al3;
            LDM_X4(ah0,ah1,ah2,ah3, aH + ks*32);
            LDM_X4(al0,al1,al2,al3, aL + ks*32);
            #pragma unroll
            for (int j = 0; j < 4; j++) {
                const int dd = d0w + j*16;
                const uint32_t xb  = smem_u32(xh) + (ks*16 + brow)*XPB + dd*2 + bcolb;
                const uint32_t xlb = smem_u32(xl) + (ks*16 + brow)*XPB + dd*2 + bcolb;
                uint32_t bh0,bh1,bh2,bh3, bl0,bl1,bl2,bl3;
                LDM_X4T(bh0,bh1,bh2,bh3, xb);
                LDM_X4T(bl0,bl1,bl2,bl3, xlb);
                mma_bf16(acc[2*j],   ah0,ah1,ah2,ah3, bh0,bh1);
                mma_bf16(acc[2*j],   ah0,ah1,ah2,ah3, bl0,bl1);
                mma_bf16(acc[2*j],   al0,al1,al2,al3, bh0,bh1);
                mma_bf16(acc[2*j+1], ah0,ah1,ah2,ah3, bh2,bh3);
                mma_bf16(acc[2*j+1], ah0,ah1,ah2,ah3, bl2,bl3);
                mma_bf16(acc[2*j+1], al0,al1,al2,al3, bh2,bh3);
            }
        }
        float* yo = (first ? g_ya : g_yb) + (size_t)b * N_ * D_;
        const int nr = n0w + (lane >> 2);
        #pragma unroll
        for (int jj = 0; jj < 8; jj++) {
            int d = d0w + jj*8 + (lane & 3)*2;
            red_add_v2(&yo[nr*D_ + d],     acc[jj][0], acc[jj][1]);
            red_add_v2(&yo[(nr+8)*D_ + d], acc[jj][2], acc[jj][3]);
        }
    }
}

// ---------------- launch ----------------------------------------------------
extern "C" void kernel_launch(void* const* d_in, const int* in_sizes, int n_in,
                              void* d_out, int out_size) {
    (void)in_sizes; (void)n_in; (void)out_size;
    const float* x = (const float*)d_in[0];
    const float* W = (const float*)d_in[1];
    float* out = (float*)d_out;

    cudaFuncSetAttribute(capsule_kernel, cudaFuncAttributeMaxDynamicSharedMemorySize, CAPS_SMEM);
    cudaFuncSetAttribute(pass_kernel,    cudaFuncAttributeMaxDynamicSharedMemorySize, PASS_SMEM);

    reduce_x_kernel<<<B_*8, 256>>>(x);                 // y0 partials + zero ya/yb

    capsule_kernel<<<dim3(N_, B_/CB), CTPB_THREADS, CAPS_SMEM>>>(W, 0, nullptr, 1); // v0, p0
    pass_kernel<<<B_*CHUNKS, TPB, PASS_SMEM>>>(x, 1);                               // iter1
    capsule_kernel<<<dim3(N_, B_/CB), CTPB_THREADS, CAPS_SMEM>>>(W, 1, nullptr, 1); // v1, p1
    pass_kernel<<<B_*CHUNKS, TPB, PASS_SMEM>>>(x, 0);                               // iter2
    capsule_kernel<<<dim3(N_, B_/CB), CTPB_THREADS, CAPS_SMEM>>>(W, 2, out, 0);     // v2 -> out
}

// round 17
// speedup vs baseline: 1.1104x; 1.0554x over previous
#include <cuda_runtime.h>
#include <cuda_bf16.h>
#include <math.h>
#include <stdint.h>

// Problem constants
#define B_  32
#define S_  1024
#define D_  256
#define N_  32
#define C_  64
#define M_  (B_*S_)

// pass kernel tiling (tensor-core version)
#define SCH 32                // s-values per block
#define CHUNKS (S_/SCH)       // 32
#define TPB 256               // 8 warps
#define XPB 528               // x smem row pitch BYTES (264 bf16; 33 x 16B, odd)
#define PPB 528               // p smem row pitch bytes
#define CTPB 80               // cT row pitch bytes (40 bf16; 5 x 16B, odd)
#define CPAD 36               // agree fp32 row stride (floats)

// smem byte offsets; cS (4608 B) aliases cth+ctl (5120 B) — live ranges disjoint
#define O_XH  0
#define O_XL  (O_XH + SCH*XPB)       // 16896
#define O_PH  (O_XL + SCH*XPB)       // 33792
#define O_PL  (O_PH + N_*PPB)        // 50688
#define O_CS  (O_PL + N_*PPB)        // 67584
#define O_CTH O_CS                   // 67584 (alias)
#define O_CTL (O_CTH + N_*CTPB)      // 70144
#define PASS_SMEM (O_CTL + N_*CTPB)  // 72704 B -> 3 CTAs/SM (218112 total)

// capsule: 8 b's per block, 512 threads, grid (N_, B_/8) = 128 blocks (ONE wave)
#define WPAD 68               // W smem row stride (floats); 17 float4/row
#define CB 8                  // b's per capsule block
#define CTPB_THREADS 512
// sW + sy + ss(4 d-quarters) + sv
#define CAPS_SMEM ((D_*WPAD + CB*D_ + 4*CB*C_ + CB*C_) * 4)  // 96256 B

// ---------------- scratch (device globals; no runtime allocation) ----------
__device__ float          g_y0p[8*B_*D_];     // per-chunk partials of (1/N) sum_s x
__device__ float          g_ya[B_*N_*D_];     // y for iter1
__device__ float          g_yb[B_*N_*D_];     // y for iter2
__device__ float          g_v [B_*N_*C_];
__device__ float          g_logits[B_*S_*N_];
__device__ __nv_bfloat16  g_phi[B_*N_*D_];
__device__ __nv_bfloat16  g_plo[B_*N_*D_];

// ---------------- PTX helpers ----------------------------------------------
__device__ __forceinline__ uint32_t smem_u32(const void* p) {
    uint32_t a;
    asm("{ .reg .u64 t; cvta.to.shared.u64 t, %1; cvt.u32.u64 %0, t; }" : "=r"(a) : "l"(p));
    return a;
}
#define LDM_X4(r0,r1,r2,r3,a) \
    asm volatile("ldmatrix.sync.aligned.m8n8.x4.shared.b16 {%0,%1,%2,%3}, [%4];" \
        : "=r"(r0),"=r"(r1),"=r"(r2),"=r"(r3) : "r"(a))
#define LDM_X2(r0,r1,a) \
    asm volatile("ldmatrix.sync.aligned.m8n8.x2.shared.b16 {%0,%1}, [%2];" \
        : "=r"(r0),"=r"(r1) : "r"(a))
#define LDM_X4T(r0,r1,r2,r3,a) \
    asm volatile("ldmatrix.sync.aligned.m8n8.x4.trans.shared.b16 {%0,%1,%2,%3}, [%4];" \
        : "=r"(r0),"=r"(r1),"=r"(r2),"=r"(r3) : "r"(a))
__device__ __forceinline__ void mma_bf16(float* c, uint32_t a0, uint32_t a1, uint32_t a2,
                                         uint32_t a3, uint32_t b0, uint32_t b1) {
    asm volatile(
        "mma.sync.aligned.m16n8k16.row.col.f32.bf16.bf16.f32 "
        "{%0,%1,%2,%3}, {%4,%5,%6,%7}, {%8,%9}, {%0,%1,%2,%3};"
        : "+f"(c[0]), "+f"(c[1]), "+f"(c[2]), "+f"(c[3])
        : "r"(a0), "r"(a1), "r"(a2), "r"(a3), "r"(b0), "r"(b1));
}
__device__ __forceinline__ void red_add_v2(float* p, float a, float b) {
    asm volatile("red.global.add.v2.f32 [%0], {%1, %2};"
        :: "l"(__cvta_generic_to_global(p)), "f"(a), "f"(b) : "memory");
}

// split a float4 into hi/lo bf16x2-pairs (uint2 each)
__device__ __forceinline__ void split4(float4 v, uint2& hh, uint2& ll) {
    __nv_bfloat162 h01 = __float22bfloat162_rn(make_float2(v.x, v.y));
    __nv_bfloat162 h23 = __float22bfloat162_rn(make_float2(v.z, v.w));
    __nv_bfloat162 l01 = __float22bfloat162_rn(make_float2(
        v.x - __bfloat162float(h01.x), v.y - __bfloat162float(h01.y)));
    __nv_bfloat162 l23 = __float22bfloat162_rn(make_float2(
        v.z - __bfloat162float(h23.x), v.w - __bfloat162float(h23.y)));
    hh = make_uint2(*(uint32_t*)&h01, *(uint32_t*)&h23);
    ll = make_uint2(*(uint32_t*)&l01, *(uint32_t*)&l23);
}

// ---------------- y0 partials + ya/yb zeroing (read-only reduction) ---------
__global__ __launch_bounds__(256) void reduce_x_kernel(const float* __restrict__ x) {
    __shared__ float sred[256*4];
    const int b  = blockIdx.x >> 3;     // 32
    const int sg = blockIdx.x & 7;      // 8 groups x 128 s
    const int t  = threadIdx.x;
    const int q  = t & 63;              // d-quad: d = 4q
    const int rg = t >> 6;              // row-group 0..3
    const size_t rowbase = (size_t)b * S_ + sg * 128;

    {
        float4 z = make_float4(0.f, 0.f, 0.f, 0.f);
        ((float4*)g_ya)[blockIdx.x*256 + t] = z;
        ((float4*)g_yb)[blockIdx.x*256 + t] = z;
    }

    float4 a = make_float4(0.f, 0.f, 0.f, 0.f);
    #pragma unroll 8
    for (int it = 0; it < 32; it++) {
        const int s = it*4 + rg;
        const float4 v = *(const float4*)(x + (rowbase + s) * D_ + 4*q);
        a.x += v.x; a.y += v.y; a.z += v.z; a.w += v.w;
    }
    *(float4*)&sred[t*4] = a;
    __syncthreads();
    if (t < 64) {
        float4 r0 = *(const float4*)&sred[t*4];
        float4 r1 = *(const float4*)&sred[(t+64)*4];
        float4 r2 = *(const float4*)&sred[(t+128)*4];
        float4 r3 = *(const float4*)&sred[(t+192)*4];
        const float sc = 1.0f / (float)N_;
        float4 o = make_float4((r0.x+r1.x+r2.x+r3.x)*sc, (r0.y+r1.y+r2.y+r3.y)*sc,
                               (r0.z+r1.z+r2.z+r3.z)*sc, (r0.w+r1.w+r2.w+r3.w)*sc);
        *(float4*)&g_y0p[(sg*B_ + b)*D_ + 4*t] = o;
    }
}

// ---------------- capsule: s = y@W, v = squash(s), p = W@v (split-bf16) -----
// grid (N_, B_/CB) = (32, 4) = 128 blocks -> one block per SM, single wave.
// PDL: W-tile load (input-only) runs BEFORE griddepsync, overlapping predecessor.
__global__ __launch_bounds__(CTPB_THREADS) void capsule_kernel(
        const float* __restrict__ W, int ysel, float* __restrict__ vout_ext, int compute_p) {
    extern __shared__ float sm[];
    float* sW = sm;                 // [D_][WPAD]
    float* sy = sW + D_*WPAD;       // [CB][D_]
    float* ss = sy + CB*D_;         // [4][CB][C_]  (four 64-d quarters)
    float* sv = ss + 4*CB*C_;       // [CB][C_]

    const int n  = blockIdx.x;
    const int b0 = blockIdx.y * CB;
    const int t  = threadIdx.x;

    // W[n] load: 4096 float4 via LDG.128 -> STS.128, 8 per thread (predecessor-independent)
    {
        const float4* Wn4 = (const float4*)(W + (size_t)n * D_ * C_);
        #pragma unroll
        for (int k = 0; k < 8; k += 4) {
            int j0 = t + (k+0)*512, j1 = t + (k+1)*512, j2 = t + (k+2)*512, j3 = t + (k+3)*512;
            float4 w0 = Wn4[j0];
            float4 w1 = Wn4[j1];
            float4 w2 = Wn4[j2];
            float4 w3 = Wn4[j3];
            *(float4*)&sW[(j0>>4)*WPAD + 4*(j0&15)] = w0;
            *(float4*)&sW[(j1>>4)*WPAD + 4*(j1&15)] = w1;
            *(float4*)&sW[(j2>>4)*WPAD + 4*(j2&15)] = w2;
            *(float4*)&sW[(j3>>4)*WPAD + 4*(j3&15)] = w3;
        }
    }

    // wait for predecessor kernel (y / g_y0p producers) before reading its output
    cudaGridDependencySynchronize();

    // y rows for CB b's: CB*D_/512 = 4 per thread
    #pragma unroll
    for (int k = 0; k < CB*D_/CTPB_THREADS; k++) {
        int i = t + k*CTPB_THREADS;
        int bb = i >> 8, d = i & 255;
        if (ysel == 0) {
            float a = 0.f;
            #pragma unroll
            for (int p8 = 0; p8 < 8; p8++) a += g_y0p[(p8*B_ + b0+bb)*D_ + d];
            sy[bb*D_ + d] = a;
        } else {
            const float* ysrc = (ysel == 1) ? g_ya : g_yb;
            sy[bb*D_ + d] = ysrc[((size_t)(b0+bb)*N_ + n)*D_ + d];
        }
    }
    __syncthreads();

    // s[b][c] = sum_d y[b][d] * W[d][c]
    // thread tile: c-quad c4 = t&15, bb = (t>>4)&7, quarter = t>>7 (64 d's)
    {
        const int c4 = t & 15, bb = (t >> 4) & 7, quarter = t >> 7;
        const float* yr = sy + bb*D_ + quarter*64;
        const float4* w4 = (const float4*)sW + (quarter*64)*(WPAD/4) + c4;  // WPAD/4 = 17
        float4 acc = make_float4(0.f, 0.f, 0.f, 0.f);
        #pragma unroll
        for (int d = 0; d < 64; d++) {
            float4 w = w4[d*17];
            float yv = yr[d];
            acc.x += yv * w.x; acc.y += yv * w.y;
            acc.z += yv * w.z; acc.w += yv * w.w;
        }
        *(float4*)&ss[quarter*CB*C_ + bb*C_ + 4*c4] = acc;
    }
    __syncthreads();

    // squash: warps 0..CB-1, warp wid handles b = b0+wid (combines 4 d-quarters)
    const int wid = t >> 5, lane = t & 31;
    if (wid < CB) {
        float a0 = 0.f, a1 = 0.f;
        #pragma unroll
        for (int h = 0; h < 4; h++) {
            a0 += ss[h*CB*C_ + wid*C_ + lane];
            a1 += ss[h*CB*C_ + wid*C_ + 32 + lane];
        }
        float sq = a0*a0 + a1*a1;
        #pragma unroll
        for (int o = 16; o > 0; o >>= 1) sq += __shfl_xor_sync(0xffffffffu, sq, o);
        float sc = (sq / (1.f + sq)) * rsqrtf(sq + 1e-8f);
        float v0 = a0 * sc, v1 = a1 * sc;
        sv[wid*C_ + lane]      = v0;
        sv[wid*C_ + 32 + lane] = v1;
        float* vo = (vout_ext ? vout_ext : g_v) + ((size_t)(b0+wid)*N_ + n)*C_;
        vo[lane]      = v0;
        vo[32 + lane] = v1;
    }
    __syncthreads();

    // p[b][d] = sum_c W[d][c] * v[b][c]; thread = (bb = t>>6, dl = t&63), 4 d's each
    if (compute_p) {
        const int bb = t >> 6, dl = t & 63;
        const float4* sv4 = (const float4*)(sv + bb*C_);
        #pragma unroll
        for (int dd = 0; dd < 4; dd++) {
            const int d = dd*64 + dl;
            const float4* wr4 = (const float4*)sW + d*(WPAD/4);
            float acc = 0.f;
            #pragma unroll
            for (int c4 = 0; c4 < 16; c4++) {
                float4 w = wr4[c4];
                float4 v = sv4[c4];
                acc += w.x*v.x + w.y*v.y + w.z*v.z + w.w*v.w;
            }
            size_t o = ((size_t)(b0+bb)*N_ + n)*D_ + d;
            __nv_bfloat16 h = __float2bfloat16(acc);
            g_phi[o] = h;
            g_plo[o] = __float2bfloat16(acc - __bfloat162float(h));
        }
    }
}

// ---------------- fused routing pass (tensor cores) --------------------------
// grid = B_*CHUNKS (1024), 256 threads, 3 CTAs/SM. Reads fp32 x, splits on the fly.
// PDL: x-tile load/split (input-only) runs BEFORE griddepsync.
__global__ __launch_bounds__(TPB, 3) void pass_kernel(const float* __restrict__ x, int first) {
    extern __shared__ char smc[];
    char* xh  = smc + O_XH;
    char* xl  = smc + O_XL;
    char* ph  = smc + O_PH;
    char* pl  = smc + O_PL;
    char* cth = smc + O_CTH;
    char* ctl = smc + O_CTL;
    float* cS = (float*)(smc + O_CS);   // aliases cth/ctl; live ranges disjoint

    const int t = threadIdx.x, wid = t >> 5, lane = t & 31;
    const int b  = blockIdx.x >> 5;
    const int ch = blockIdx.x & 31;
    const int s0 = ch * SCH;

    // load x tile fp32 and split-convert to bf16 hi/lo planes (predecessor-independent)
    {
        const float4* xg = (const float4*)(x + ((size_t)(b*S_ + s0)) * D_);
        #pragma unroll
        for (int i = t; i < SCH*64; i += TPB) {   // 2048 float4
            int s = i >> 6, dq = i & 63;
            uint2 hh, ll;
            split4(xg[i], hh, ll);
            *(uint2*)(xh + s*XPB + dq*8) = hh;
            *(uint2*)(xl + s*XPB + dq*8) = ll;
        }
    }

    // wait for predecessor (capsule: g_phi/g_plo producer) before reading p
    cudaGridDependencySynchronize();

    {
        const uint4* qh = (const uint4*)(g_phi + (size_t)b * N_ * D_);
        const uint4* ql = (const uint4*)(g_plo + (size_t)b * N_ * D_);
        #pragma unroll
        for (int i = t; i < N_*32; i += TPB) {
            int n = i >> 5, q = i & 31;
            *(uint4*)(ph + n*PPB + q*16) = qh[i];
            *(uint4*)(pl + n*PPB + q*16) = ql[i];
        }
    }
    __syncthreads();

    // phase 2: agree = X (32s x 256k) @ P^T -> warp tile m16(s) x n8(n), full K
    {
        const int pm = wid & 1, pn = wid >> 1;       // 2 x 4 warp grid
        const int s0w = pm * 16, n0w = pn * 8;
        const uint32_t aH = smem_u32(xh) + (s0w + (lane & 15))*XPB + (lane >> 4)*16;
        const uint32_t aL = smem_u32(xl) + (s0w + (lane & 15))*XPB + (lane >> 4)*16;
        const uint32_t bH = smem_u32(ph) + (n0w + (lane & 7))*PPB + ((lane >> 3) & 1)*16;
        const uint32_t bL = smem_u32(pl) + (n0w + (lane & 7))*PPB + ((lane >> 3) & 1)*16;
        float c1[4] = {0.f,0.f,0.f,0.f};
        float c2[4] = {0.f,0.f,0.f,0.f};
        float c3[4] = {0.f,0.f,0.f,0.f};
        #pragma unroll
        for (int k = 0; k < 16; k++) {
            uint32_t ah0,ah1,ah2,ah3, al0,al1,al2,al3, bh0,bh1, bl0,bl1;
            LDM_X4(ah0,ah1,ah2,ah3, aH + k*32);
            LDM_X4(al0,al1,al2,al3, aL + k*32);
            LDM_X2(bh0,bh1, bH + k*32);
            LDM_X2(bl0,bl1, bL + k*32);
            mma_bf16(c1, ah0,ah1,ah2,ah3, bh0,bh1);   // hi*hi
            mma_bf16(c2, ah0,ah1,ah2,ah3, bl0,bl1);   // hi*lo
            mma_bf16(c3, al0,al1,al2,al3, bh0,bh1);   // lo*hi
        }
        const int sr = s0w + (lane >> 2), nc = n0w + (lane & 3)*2;
        cS[sr*CPAD + nc]         = c1[0] + c2[0] + c3[0];
        cS[sr*CPAD + nc + 1]     = c1[1] + c2[1] + c3[1];
        cS[(sr+8)*CPAD + nc]     = c1[2] + c2[2] + c3[2];
        cS[(sr+8)*CPAD + nc + 1] = c1[3] + c2[3] + c3[3];
    }
    __syncthreads();

    // softmax over n per s-row, split read -> barrier -> compute+write (cS alias)
    {
        float lg[4];
        #pragma unroll
        for (int r = 0; r < 4; r++) {
            int s = wid*4 + r;
            lg[r] = cS[s*CPAD + lane];
            size_t li = ((size_t)b * S_ + s0 + s) * N_ + lane;
            if (first) g_logits[li] = lg[r];
            else       lg[r] += g_logits[li];
        }
        __syncthreads();
        #pragma unroll
        for (int r = 0; r < 4; r++) {
            int s = wid*4 + r;
            float v = lg[r];
            float mx = v;
            #pragma unroll
            for (int o = 16; o > 0; o >>= 1) mx = fmaxf(mx, __shfl_xor_sync(0xffffffffu, mx, o));
            float e = expf(v - mx);
            float sum = e;
            #pragma unroll
            for (int o = 16; o > 0; o >>= 1) sum += __shfl_xor_sync(0xffffffffu, sum, o);
            float cv = e / sum;
            __nv_bfloat16 hh = __float2bfloat16(cv);
            *(__nv_bfloat16*)(cth + lane*CTPB + s*2) = hh;
            *(__nv_bfloat16*)(ctl + lane*CTPB + s*2) =
                __float2bfloat16(cv - __bfloat162float(hh));
        }
    }
    __syncthreads();

    // phase 3: y = C^T (32n x 32k(s)) @ X (32s x 256d) -> warp m16(n) x 64d
    {
        const int wm = wid & 1, wd = wid >> 1;       // 2 x 4 warp grid
        const int n0w = wm * 16, d0w = wd * 64;
        const uint32_t aH = smem_u32(cth) + (n0w + (lane & 15))*CTPB + (lane >> 4)*16;
        const uint32_t aL = smem_u32(ctl) + (n0w + (lane & 15))*CTPB + (lane >> 4)*16;
        const int part  = lane >> 3;
        const int brow  = (part & 1)*8 + (lane & 7);
        const int bcolb = (part >> 1)*16;
        float acc[8][4];
        #pragma unroll
        for (int i = 0; i < 8; i++)
            #pragma unroll
            for (int j = 0; j < 4; j++) acc[i][j] = 0.f;

        #pragma unroll
        for (int ks = 0; ks < 2; ks++) {
            uint32_t ah0,ah1,ah2,ah3, al0,al1,al2,al3;
            LDM_X4(ah0,ah1,ah2,ah3, aH + ks*32);
            LDM_X4(al0,al1,al2,al3, aL + ks*32);
            #pragma unroll
            for (int j = 0; j < 4; j++) {
                const int dd = d0w + j*16;
                const uint32_t xb  = smem_u32(xh) + (ks*16 + brow)*XPB + dd*2 + bcolb;
                const uint32_t xlb = smem_u32(xl) + (ks*16 + brow)*XPB + dd*2 + bcolb;
                uint32_t bh0,bh1,bh2,bh3, bl0,bl1,bl2,bl3;
                LDM_X4T(bh0,bh1,bh2,bh3, xb);
                LDM_X4T(bl0,bl1,bl2,bl3, xlb);
                mma_bf16(acc[2*j],   ah0,ah1,ah2,ah3, bh0,bh1);
                mma_bf16(acc[2*j],   ah0,ah1,ah2,ah3, bl0,bl1);
                mma_bf16(acc[2*j],   al0,al1,al2,al3, bh0,bh1);
                mma_bf16(acc[2*j+1], ah0,ah1,ah2,ah3, bh2,bh3);
                mma_bf16(acc[2*j+1], ah0,ah1,ah2,ah3, bl2,bl3);
                mma_bf16(acc[2*j+1], al0,al1,al2,al3, bh2,bh3);
            }
        }
        float* yo = (first ? g_ya : g_yb) + (size_t)b * N_ * D_;
        const int nr = n0w + (lane >> 2);
        #pragma unroll
        for (int jj = 0; jj < 8; jj++) {
            int d = d0w + jj*8 + (lane & 3)*2;
            red_add_v2(&yo[nr*D_ + d],     acc[jj][0], acc[jj][1]);
            red_add_v2(&yo[(nr+8)*D_ + d], acc[jj][2], acc[jj][3]);
        }
    }
}

// ---------------- launch ----------------------------------------------------
extern "C" void kernel_launch(void* const* d_in, const int* in_sizes, int n_in,
                              void* d_out, int out_size) {
    (void)in_sizes; (void)n_in; (void)out_size;
    const float* x = (const float*)d_in[0];
    const float* W = (const float*)d_in[1];
    float* out = (float*)d_out;

    cudaFuncSetAttribute(capsule_kernel, cudaFuncAttributeMaxDynamicSharedMemorySize, CAPS_SMEM);
    cudaFuncSetAttribute(pass_kernel,    cudaFuncAttributeMaxDynamicSharedMemorySize, PASS_SMEM);

    // PDL attribute: dependent kernels may launch while predecessor runs;
    // their griddepsync gates consumption of predecessor output.
    cudaLaunchAttribute pdl[1];
    pdl[0].id = cudaLaunchAttributeProgrammaticStreamSerialization;
    pdl[0].val.programmaticStreamSerializationAllowed = 1;

    cudaLaunchConfig_t ccap = {};
    ccap.gridDim = dim3(N_, B_/CB);
    ccap.blockDim = dim3(CTPB_THREADS);
    ccap.dynamicSmemBytes = CAPS_SMEM;
    ccap.stream = 0;
    ccap.attrs = pdl;
    ccap.numAttrs = 1;

    cudaLaunchConfig_t cpass = {};
    cpass.gridDim = dim3(B_*CHUNKS);
    cpass.blockDim = dim3(TPB);
    cpass.dynamicSmemBytes = PASS_SMEM;
    cpass.stream = 0;
    cpass.attrs = pdl;
    cpass.numAttrs = 1;

    reduce_x_kernel<<<B_*8, 256>>>(x);                 // y0 partials + zero ya/yb

    float* nullf = nullptr;
    cudaLaunchKernelEx(&ccap,  capsule_kernel, W, 0, nullf, 1);   // v0, p0
    cudaLaunchKernelEx(&cpass, pass_kernel,    x, 1);             // iter1 -> g_ya
    cudaLaunchKernelEx(&ccap,  capsule_kernel, W, 1, nullf, 1);   // v1, p1
    cudaLaunchKernelEx(&cpass, pass_kernel,    x, 0);             // iter2 -> g_yb
    cudaLaunchKernelEx(&ccap,  capsule_kernel, W, 2, out, 0);     // v2 -> d_out
}